// round 1
// baseline (speedup 1.0000x reference)
#include <cuda_runtime.h>
#include <cuda_bf16.h>
#include <math.h>

// Problem constants
#define Bconst   262144
#define Dd       16
#define CTXd     128
#define Hd       192
#define INd      145        // D + CTX + 1
#define MROWS    64         // rows (samples) per CTA
#define MTILE    128        // primal + tangent stacked
#define THREADS  256
#define TM       8
#define TN       12
#define KT       16
#define STR      193        // smem row stride (floats) for activation buffers

// Dynamic smem layout (floats)
#define OFF_BUFA 0
#define SZ_BUF   (MTILE * STR)            // 24704
#define OFF_BUFB (OFF_BUFA + SZ_BUF)
#define OFF_WT   (OFF_BUFB + SZ_BUF)      // 49408
#define SZ_WT    (KT * 192)               // 3072
#define OFF_EPS  (OFF_WT + SZ_WT)         // 52480
#define SZ_EPS   (MROWS * Dd)             // 1024
#define SMEM_FLOATS (OFF_EPS + SZ_EPS)    // 53504
#define SMEM_BYTES  (SMEM_FLOATS * 4)     // 214016

__device__ __forceinline__ void gemm_n192(const float* __restrict__ gW, int K,
                                          const float* __restrict__ sIn,
                                          float* __restrict__ sOut,
                                          float* __restrict__ sWt, int tid)
{
    const int tm = tid >> 4;   // 0..15  (8-row group)
    const int tn = tid & 15;   // 0..15  (12-col group)
    float acc[TM][TN];
#pragma unroll
    for (int i = 0; i < TM; i++)
#pragma unroll
        for (int j = 0; j < TN; j++) acc[i][j] = 0.0f;

    const float* aBase = sIn + tm * TM * STR;

    for (int k0 = 0; k0 < K; k0 += KT) {
        const int kt = min(KT, K - k0);
        __syncthreads();
        {   // cooperative W tile load: kt rows x 192 cols (contiguous in gmem)
            const float4* src = (const float4*)(gW + (size_t)k0 * 192);
            float4* dst = (float4*)sWt;
            const int n4 = kt * 48;
            for (int e = tid; e < n4; e += THREADS) dst[e] = src[e];
        }
        __syncthreads();

#pragma unroll 4
        for (int kk = 0; kk < kt; ++kk) {
            const float4* wp = (const float4*)(sWt + kk * 192 + tn * TN);
            const float4 w0 = wp[0], w1 = wp[1], w2 = wp[2];
#pragma unroll
            for (int i = 0; i < TM; i++) {
                const float a = aBase[i * STR + k0 + kk];
                acc[i][0]  += a * w0.x;  acc[i][1]  += a * w0.y;
                acc[i][2]  += a * w0.z;  acc[i][3]  += a * w0.w;
                acc[i][4]  += a * w1.x;  acc[i][5]  += a * w1.y;
                acc[i][6]  += a * w1.z;  acc[i][7]  += a * w1.w;
                acc[i][8]  += a * w2.x;  acc[i][9]  += a * w2.y;
                acc[i][10] += a * w2.z;  acc[i][11] += a * w2.w;
            }
        }
    }

    float* o = sOut + tm * TM * STR + tn * TN;
#pragma unroll
    for (int i = 0; i < TM; i++)
#pragma unroll
        for (int j = 0; j < TN; j++) o[i * STR + j] = acc[i][j];
    __syncthreads();
}

// Fused exact-GELU forward + derivative*tangent, in place.
// buf rows [0,64): preact A (bias added here); rows [64,128): tangent U.
__device__ __forceinline__ void gelu_jvp_pass(float* __restrict__ buf,
                                              const float* __restrict__ bias,
                                              float* __restrict__ sWt, int tid)
{
    if (tid < 192) sWt[tid] = bias[tid];
    __syncthreads();
    for (int e = tid; e < MROWS * 192; e += THREADS) {
        const int r = e / 192;
        const int c = e - r * 192;
        const float a = buf[r * STR + c] + sWt[c];
        const float u = buf[(r + MROWS) * STR + c];
        const float cdf = 0.5f * (1.0f + erff(a * 0.70710678118654752f));
        const float pdf = 0.3989422804014327f * __expf(-0.5f * a * a);
        buf[r * STR + c] = a * cdf;                    // gelu(a)
        buf[(r + MROWS) * STR + c] = (cdf + a * pdf) * u; // gelu'(a)*u
    }
    __syncthreads();
}

__global__ void __launch_bounds__(THREADS, 1)
odefunc_kernel(const float* __restrict__ t,
               const float* __restrict__ y,
               const float* __restrict__ h,
               const float* __restrict__ eps,
               const float* __restrict__ W1, const float* __restrict__ b1,
               const float* __restrict__ W2, const float* __restrict__ b2,
               const float* __restrict__ W3, const float* __restrict__ b3,
               float* __restrict__ out, int Bsz)
{
    extern __shared__ __align__(16) float smem[];
    float* bufA = smem + OFF_BUFA;
    float* bufB = smem + OFF_BUFB;
    float* sWt  = smem + OFF_WT;
    float* epsS = smem + OFF_EPS;

    const int tid  = threadIdx.x;
    const int row0 = blockIdx.x * MROWS;

    float* outF    = out;
    float* outLogp = out + (size_t)Bsz * Dd;
    float* outDh   = out + (size_t)Bsz * (Dd + 1);

    // dh = zeros (coalesced)
    {
        float* dhp = outDh + (size_t)row0 * CTXd;
        for (int e = tid; e < MROWS * CTXd; e += THREADS) dhp[e] = 0.0f;
    }

    const float tval = t[0];

    // Build input tile: rows [0,64) = [y, h, t]; rows [64,128) = [eps, 0...]
    for (int e = tid; e < MROWS * INd; e += THREADS) {
        const int r = e / INd;
        const int c = e - r * INd;
        float v;
        if (c < Dd)            v = y[(size_t)(row0 + r) * Dd + c];
        else if (c < Dd + CTXd) v = h[(size_t)(row0 + r) * CTXd + (c - Dd)];
        else                   v = tval;
        bufA[r * STR + c] = v;
    }
    for (int e = tid; e < MROWS * INd; e += THREADS) {
        const int r = e / INd;
        const int c = e - r * INd;
        float v = 0.0f;
        if (c < Dd) {
            v = eps[(size_t)(row0 + r) * Dd + c];
            epsS[r * Dd + c] = v;
        }
        bufA[(MROWS + r) * STR + c] = v;
    }

    // Layer 1: [X;EPSpad] @ W1  (K=145) -> bufB, then fused GELU/JVP
    gemm_n192(W1, INd, bufA, bufB, sWt, tid);
    gelu_jvp_pass(bufB, b1, sWt, tid);

    // Layer 2: [Z1;DU1] @ W2 (K=192) -> bufA, then fused GELU/JVP
    gemm_n192(W2, Hd, bufB, bufA, sWt, tid);
    gelu_jvp_pass(bufA, b2, sWt, tid);

    // Layer 3: [Z2;DU2] @ W3 (K=192, N=16) -> registers
    const int tm = tid >> 4;
    const int tn = tid & 15;
    float acc3[TM];
#pragma unroll
    for (int i = 0; i < TM; i++) acc3[i] = 0.0f;
    {
        const float* aBase = bufA + tm * TM * STR;
        for (int k0 = 0; k0 < Hd; k0 += KT) {
            __syncthreads();
            if (tid < KT * Dd) sWt[tid] = W3[(size_t)k0 * Dd + tid];
            __syncthreads();
#pragma unroll
            for (int kk = 0; kk < KT; kk++) {
                const float b = sWt[kk * Dd + tn];
#pragma unroll
                for (int i = 0; i < TM; i++)
                    acc3[i] += aBase[i * STR + k0 + kk] * b;
            }
        }
    }

    // Epilogue
    if (tm < 8) {
        // primal rows -> f = z2@W3 + b3
        const float b3v = b3[tn];
#pragma unroll
        for (int i = 0; i < TM; i++) {
            const int r = tm * TM + i;                 // 0..63
            outF[(size_t)(row0 + r) * Dd + tn] = acc3[i] + b3v;
        }
    } else {
        // tangent rows -> dlogp = -sum_c Jeps[r][c]*eps[r][c]
        const int rbase = (tm - 8) * TM;
#pragma unroll
        for (int i = 0; i < TM; i++) {
            const int r = rbase + i;                   // 0..63
            float p = acc3[i] * epsS[r * Dd + tn];
            p += __shfl_xor_sync(0xffffffffu, p, 1);
            p += __shfl_xor_sync(0xffffffffu, p, 2);
            p += __shfl_xor_sync(0xffffffffu, p, 4);
            p += __shfl_xor_sync(0xffffffffu, p, 8);
            if (tn == 0) outLogp[row0 + r] = -p;
        }
    }
}

extern "C" void kernel_launch(void* const* d_in, const int* in_sizes, int n_in,
                              void* d_out, int out_size)
{
    const float* t   = (const float*)d_in[0];
    const float* y   = (const float*)d_in[1];
    // d_in[2] = logp (unused)
    const float* h   = (const float*)d_in[3];
    const float* eps = (const float*)d_in[4];
    const float* W1  = (const float*)d_in[5];
    const float* b1  = (const float*)d_in[6];
    const float* W2  = (const float*)d_in[7];
    const float* b2  = (const float*)d_in[8];
    const float* W3  = (const float*)d_in[9];
    const float* b3  = (const float*)d_in[10];

    const int Bsz = in_sizes[1] / Dd;

    cudaFuncSetAttribute(odefunc_kernel,
                         cudaFuncAttributeMaxDynamicSharedMemorySize,
                         SMEM_BYTES);

    const int grid = Bsz / MROWS;
    odefunc_kernel<<<grid, THREADS, SMEM_BYTES>>>(
        t, y, h, eps, W1, b1, W2, b2, W3, b3, (float*)d_out, Bsz);
}

// round 3
// speedup vs baseline: 1.5970x; 1.5970x over previous
#include <cuda_runtime.h>
#include <cuda_bf16.h>
#include <cstdint>
#include <math.h>

// ---------------- problem constants ----------------
#define Dd      16
#define CTXd    128
#define Hd      192
#define MROWS   64
#define THREADS 256

// weight image geometry: [N][Kpad] bf16, row stride chosen for conflict-free ldmatrix
#define STR1    168      // W1: K=145 padded to 160, stride 168 (336B rows)
#define STR2    200      // W2/W3: K=192, stride 200 (400B rows)
#define T1ELEM  (192*STR1)   // 32256
#define T2ELEM  (192*STR2)   // 38400
#define T3ELEM  (16*STR2)    // 3200
#define T1B     (T1ELEM*2)   // 64512 bytes per term
#define T2B     (T2ELEM*2)   // 76800
#define T3B     (T3ELEM*2)   // 6400

// smem layout (bytes)
#define SM_W    0
#define SM_A    153600                  // aShare: [64][200] float
#define SM_BIAS (SM_A + 64*200*4)       // 204800
#define SM_TOT  (SM_BIAS + 768)         // 205568

__device__ __align__(16) __nv_bfloat16 g_w1[2*T1ELEM];
__device__ __align__(16) __nv_bfloat16 g_w2[2*T2ELEM];
__device__ __align__(16) __nv_bfloat16 g_w3[2*T3ELEM];

// ---------------- prep: transpose + split + pad ----------------
__global__ void prep_weights(const float* __restrict__ W1,
                             const float* __restrict__ W2,
                             const float* __restrict__ W3)
{
    int idx = blockIdx.x * blockDim.x + threadIdx.x;
    const float* W; __nv_bfloat16* img; int Kin, N, STR_, TERM, i;
    if (idx < T1ELEM)               { i = idx;                 W = W1; img = g_w1; Kin = 145; N = 192; STR_ = STR1; TERM = T1ELEM; }
    else if (idx < T1ELEM + T2ELEM) { i = idx - T1ELEM;        W = W2; img = g_w2; Kin = 192; N = 192; STR_ = STR2; TERM = T2ELEM; }
    else if (idx < T1ELEM + T2ELEM + T3ELEM)
                                    { i = idx - T1ELEM - T2ELEM; W = W3; img = g_w3; Kin = 192; N = 16; STR_ = STR2; TERM = T3ELEM; }
    else return;
    int n = i / STR_;
    int k = i - n * STR_;
    float w = (k < Kin) ? W[(size_t)k * N + n] : 0.0f;
    __nv_bfloat16 hi = __float2bfloat16_rn(w);
    __nv_bfloat16 lo = __float2bfloat16_rn(w - __bfloat162float(hi));
    img[i] = hi;
    img[TERM + i] = lo;
}

// ---------------- device helpers ----------------
__device__ __forceinline__ uint32_t smem_u32(const void* p) {
    uint32_t a;
    asm("{ .reg .u64 t; cvta.to.shared.u64 t, %1; cvt.u32.u64 %0, t; }" : "=r"(a) : "l"(p));
    return a;
}
__device__ __forceinline__ void cpa16(uint32_t dst, const void* src) {
    asm volatile("cp.async.cg.shared.global [%0], [%1], 16;" :: "r"(dst), "l"(src) : "memory");
}
__device__ __forceinline__ void cpa_flush() {
    asm volatile("cp.async.commit_group;\n\tcp.async.wait_group 0;" ::: "memory");
}
__device__ __forceinline__ void ldsm4(uint32_t& r0, uint32_t& r1, uint32_t& r2, uint32_t& r3, uint32_t addr) {
    asm volatile("ldmatrix.sync.aligned.m8n8.x4.shared.b16 {%0,%1,%2,%3}, [%4];"
                 : "=r"(r0), "=r"(r1), "=r"(r2), "=r"(r3) : "r"(addr));
}
__device__ __forceinline__ void mma16816(float (&d)[4],
    uint32_t a0, uint32_t a1, uint32_t a2, uint32_t a3, uint32_t b0, uint32_t b1)
{
    asm volatile("mma.sync.aligned.m16n8k16.row.col.f32.bf16.bf16.f32 "
                 "{%0,%1,%2,%3}, {%4,%5,%6,%7}, {%8,%9}, {%0,%1,%2,%3};"
                 : "+f"(d[0]), "+f"(d[1]), "+f"(d[2]), "+f"(d[3])
                 : "r"(a0), "r"(a1), "r"(a2), "r"(a3), "r"(b0), "r"(b1));
}
__device__ __forceinline__ void split2(float v0, float v1, uint32_t& uhi, uint32_t& ulo) {
    __nv_bfloat16 h0 = __float2bfloat16_rn(v0);
    __nv_bfloat16 h1 = __float2bfloat16_rn(v1);
    float r0 = v0 - __bfloat162float(h0);
    float r1 = v1 - __bfloat162float(h1);
    __nv_bfloat16 l0 = __float2bfloat16_rn(r0);
    __nv_bfloat16 l1 = __float2bfloat16_rn(r1);
    uhi = ((uint32_t)__bfloat16_as_ushort(h1) << 16) | (uint32_t)__bfloat16_as_ushort(h0);
    ulo = ((uint32_t)__bfloat16_as_ushort(l1) << 16) | (uint32_t)__bfloat16_as_ushort(l0);
}

// one k-step across NP n-tile-pairs, 3 split terms
template<int NP, int STRIDE, int TERMB>
__device__ __forceinline__ void mma_kstep(float (*acc)[4],
    uint32_t ah0, uint32_t ah1, uint32_t ah2, uint32_t ah3,
    uint32_t al0, uint32_t al1, uint32_t al2, uint32_t al3,
    uint32_t wbase, int kt, int laneN, int laneK8)
{
#pragma unroll
    for (int p = 0; p < NP; p++) {
        uint32_t addr = wbase + (uint32_t)((((p * 16 + laneN) * STRIDE) + kt * 16 + laneK8) * 2);
        uint32_t bh0, bh1, bh2, bh3, bl0, bl1, bl2, bl3;
        ldsm4(bh0, bh1, bh2, bh3, addr);
        ldsm4(bl0, bl1, bl2, bl3, addr + TERMB);
        mma16816(acc[2*p],   ah0, ah1, ah2, ah3, bh0, bh1);
        mma16816(acc[2*p],   al0, al1, al2, al3, bh0, bh1);
        mma16816(acc[2*p],   ah0, ah1, ah2, ah3, bl0, bl1);
        mma16816(acc[2*p+1], ah0, ah1, ah2, ah3, bh2, bh3);
        mma16816(acc[2*p+1], al0, al1, al2, al3, bh2, bh3);
        mma16816(acc[2*p+1], ah0, ah1, ah2, ah3, bl2, bl3);
    }
}

__device__ __forceinline__ float featP(const float* __restrict__ yb,
                                       const float* __restrict__ hb,
                                       float tval, int s, int c)
{
    if (c < 16)  return __ldg(yb + (size_t)s * 16 + c);
    if (c < 144) return __ldg(hb + (size_t)s * 128 + (c - 16));
    return (c == 144) ? tval : 0.0f;
}

// ---------------- main kernel ----------------
__global__ void __launch_bounds__(THREADS, 1)
odefunc_mma(const float* __restrict__ t,
            const float* __restrict__ y,
            const float* __restrict__ h,
            const float* __restrict__ eps,
            const float* __restrict__ b1,
            const float* __restrict__ b2,
            const float* __restrict__ b3,
            float* __restrict__ out, int Bsz)
{
    extern __shared__ __align__(16) char smem[];
    const uint32_t swu = smem_u32(smem);           // weight buffer base (offset 0)
    float* sA    = (float*)(smem + SM_A);          // [64][200] preactivation exchange
    float* sBias = (float*)(smem + SM_BIAS);

    const int tid  = threadIdx.x;
    const int w    = tid >> 5;
    const int lane = tid & 31;
    const int gid  = lane >> 2;
    const int tig  = lane & 3;
    const bool primalW = (w < 4);
    const int laneN  = (lane & 7) + ((lane >> 4) & 1) * 8;
    const int laneK8 = ((lane >> 3) & 1) * 8;
    const int s0 = (w & 3) * 16 + gid;   // sample row (0..63)
    const int s1 = s0 + 8;

    const int row0 = blockIdx.x * MROWS;
    float* outF    = out;
    float* outLogp = out + (size_t)Bsz * Dd;
    float* outDh   = out + (size_t)Bsz * (Dd + 1);

    const float* yb = y   + (size_t)row0 * Dd;
    const float* hb = h   + (size_t)row0 * CTXd;
    const float* eb = eps + (size_t)row0 * Dd;

    // ---- prologue: zero dh, stage b1 + W1 ----
    {
        float4* dhp = (float4*)(outDh + (size_t)row0 * CTXd);
        const float4 z4 = make_float4(0.f, 0.f, 0.f, 0.f);
        for (int i = tid; i < MROWS * CTXd / 4; i += THREADS) dhp[i] = z4;
    }
    if (tid < 192) sBias[tid] = __ldg(b1 + tid);
    for (int i = tid; i < 2 * T1B / 16; i += THREADS)
        cpa16(swu + i * 16, (const char*)g_w1 + i * 16);
    cpa_flush();
    __syncthreads();

    // =================== layer 1 ===================
    float acc[24][4];
#pragma unroll
    for (int j = 0; j < 24; j++)
#pragma unroll
        for (int q = 0; q < 4; q++) acc[j][q] = 0.0f;

    if (primalW) {
        const float tval = __ldg(t);
#pragma unroll 1
        for (int kt = 0; kt < 10; kt++) {
            const int c0 = kt * 16 + 2 * tig;
            float v00 = featP(yb, hb, tval, s0, c0);
            float v01 = featP(yb, hb, tval, s0, c0 + 1);
            float v02 = featP(yb, hb, tval, s0, c0 + 8);
            float v03 = featP(yb, hb, tval, s0, c0 + 9);
            float v10 = featP(yb, hb, tval, s1, c0);
            float v11 = featP(yb, hb, tval, s1, c0 + 1);
            float v12 = featP(yb, hb, tval, s1, c0 + 8);
            float v13 = featP(yb, hb, tval, s1, c0 + 9);
            uint32_t ah0, ah1, ah2, ah3, al0, al1, al2, al3;
            split2(v00, v01, ah0, al0);
            split2(v10, v11, ah1, al1);
            split2(v02, v03, ah2, al2);
            split2(v12, v13, ah3, al3);
            mma_kstep<12, STR1, T1B>(acc, ah0, ah1, ah2, ah3, al0, al1, al2, al3,
                                     swu, kt, laneN, laneK8);
        }
    } else {
        // tangent rows: nonzero only for k<16 (eps)
        const int c0 = 2 * tig;
        float v00 = __ldg(eb + (size_t)s0 * 16 + c0);
        float v01 = __ldg(eb + (size_t)s0 * 16 + c0 + 1);
        float v02 = __ldg(eb + (size_t)s0 * 16 + c0 + 8);
        float v03 = __ldg(eb + (size_t)s0 * 16 + c0 + 9);
        float v10 = __ldg(eb + (size_t)s1 * 16 + c0);
        float v11 = __ldg(eb + (size_t)s1 * 16 + c0 + 1);
        float v12 = __ldg(eb + (size_t)s1 * 16 + c0 + 8);
        float v13 = __ldg(eb + (size_t)s1 * 16 + c0 + 9);
        uint32_t ah0, ah1, ah2, ah3, al0, al1, al2, al3;
        split2(v00, v01, ah0, al0);
        split2(v10, v11, ah1, al1);
        split2(v02, v03, ah2, al2);
        split2(v12, v13, ah3, al3);
        mma_kstep<12, STR1, T1B>(acc, ah0, ah1, ah2, ah3, al0, al1, al2, al3,
                                 swu, 0, laneN, laneK8);
    }

    // ---- epilogue 1: bias + GELU / JVP via smem preact exchange ----
    if (primalW) {
#pragma unroll
        for (int j = 0; j < 24; j++)
#pragma unroll
            for (int q = 0; q < 4; q++) {
                const int col = j * 8 + 2 * tig + (q & 1);
                const int sr  = (q < 2) ? s0 : s1;
                float av = acc[j][q] + sBias[col];
                sA[sr * 200 + col] = av;
                acc[j][q] = av;
            }
    }
    __syncthreads();
#pragma unroll
    for (int j = 0; j < 24; j++)
#pragma unroll
        for (int q = 0; q < 4; q++) {
            const int col = j * 8 + 2 * tig + (q & 1);
            const int sr  = (q < 2) ? s0 : s1;
            if (primalW) {
                float a = acc[j][q];
                float cdf = 0.5f * (1.0f + erff(a * 0.70710678118654752f));
                acc[j][q] = a * cdf;
            } else {
                float a  = sA[sr * 200 + col];
                float dv = acc[j][q];
                float cdf = 0.5f * (1.0f + erff(a * 0.70710678118654752f));
                float pdf = 0.3989422804014327f * __expf(-0.5f * a * a);
                acc[j][q] = (cdf + a * pdf) * dv;
            }
        }
    __syncthreads();

    // stage b2 + W2
    if (tid < 192) sBias[tid] = __ldg(b2 + tid);
    for (int i = tid; i < 2 * T2B / 16; i += THREADS)
        cpa16(swu + i * 16, (const char*)g_w2 + i * 16);
    cpa_flush();
    __syncthreads();

    // =================== layer 2 ===================
    float accB[24][4];
#pragma unroll
    for (int j = 0; j < 24; j++)
#pragma unroll
        for (int q = 0; q < 4; q++) accB[j][q] = 0.0f;

#pragma unroll
    for (int kt = 0; kt < 12; kt++) {
        uint32_t ah0, ah1, ah2, ah3, al0, al1, al2, al3;
        split2(acc[2*kt][0],   acc[2*kt][1],   ah0, al0);
        split2(acc[2*kt][2],   acc[2*kt][3],   ah1, al1);
        split2(acc[2*kt+1][0], acc[2*kt+1][1], ah2, al2);
        split2(acc[2*kt+1][2], acc[2*kt+1][3], ah3, al3);
        mma_kstep<12, STR2, T2B>(accB, ah0, ah1, ah2, ah3, al0, al1, al2, al3,
                                 swu, kt, laneN, laneK8);
    }

    // ---- epilogue 2 ----
    if (primalW) {
#pragma unroll
        for (int j = 0; j < 24; j++)
#pragma unroll
            for (int q = 0; q < 4; q++) {
                const int col = j * 8 + 2 * tig + (q & 1);
                const int sr  = (q < 2) ? s0 : s1;
                float av = accB[j][q] + sBias[col];
                sA[sr * 200 + col] = av;
                accB[j][q] = av;
            }
    }
    __syncthreads();
#pragma unroll
    for (int j = 0; j < 24; j++)
#pragma unroll
        for (int q = 0; q < 4; q++) {
            const int col = j * 8 + 2 * tig + (q & 1);
            const int sr  = (q < 2) ? s0 : s1;
            if (primalW) {
                float a = accB[j][q];
                float cdf = 0.5f * (1.0f + erff(a * 0.70710678118654752f));
                accB[j][q] = a * cdf;
            } else {
                float a  = sA[sr * 200 + col];
                float dv = accB[j][q];
                float cdf = 0.5f * (1.0f + erff(a * 0.70710678118654752f));
                float pdf = 0.3989422804014327f * __expf(-0.5f * a * a);
                accB[j][q] = (cdf + a * pdf) * dv;
            }
        }
    __syncthreads();

    // stage W3
    for (int i = tid; i < 2 * T3B / 16; i += THREADS)
        cpa16(swu + i * 16, (const char*)g_w3 + i * 16);
    cpa_flush();
    __syncthreads();

    // =================== layer 3 (N=16) ===================
    float acc3[2][4];
#pragma unroll
    for (int j = 0; j < 2; j++)
#pragma unroll
        for (int q = 0; q < 4; q++) acc3[j][q] = 0.0f;

#pragma unroll
    for (int kt = 0; kt < 12; kt++) {
        uint32_t ah0, ah1, ah2, ah3, al0, al1, al2, al3;
        split2(accB[2*kt][0],   accB[2*kt][1],   ah0, al0);
        split2(accB[2*kt][2],   accB[2*kt][3],   ah1, al1);
        split2(accB[2*kt+1][0], accB[2*kt+1][1], ah2, al2);
        split2(accB[2*kt+1][2], accB[2*kt+1][3], ah3, al3);
        mma_kstep<1, STR2, T3B>(acc3, ah0, ah1, ah2, ah3, al0, al1, al2, al3,
                                swu, kt, laneN, laneK8);
    }

    // ---- final epilogue ----
    if (primalW) {
#pragma unroll
        for (int j = 0; j < 2; j++) {
            const int c = j * 8 + 2 * tig;
            const float bb0 = __ldg(b3 + c);
            const float bb1 = __ldg(b3 + c + 1);
            float2 o0 = make_float2(acc3[j][0] + bb0, acc3[j][1] + bb1);
            float2 o1 = make_float2(acc3[j][2] + bb0, acc3[j][3] + bb1);
            *(float2*)(outF + (size_t)(row0 + s0) * Dd + c) = o0;
            *(float2*)(outF + (size_t)(row0 + s1) * Dd + c) = o1;
        }
    } else {
        float dot0 = 0.f, dot1 = 0.f;
#pragma unroll
        for (int j = 0; j < 2; j++) {
            const int c = j * 8 + 2 * tig;
            dot0 += acc3[j][0] * __ldg(eb + (size_t)s0 * 16 + c)
                  + acc3[j][1] * __ldg(eb + (size_t)s0 * 16 + c + 1);
            dot1 += acc3[j][2] * __ldg(eb + (size_t)s1 * 16 + c)
                  + acc3[j][3] * __ldg(eb + (size_t)s1 * 16 + c + 1);
        }
        dot0 += __shfl_xor_sync(0xffffffffu, dot0, 1);
        dot0 += __shfl_xor_sync(0xffffffffu, dot0, 2);
        dot1 += __shfl_xor_sync(0xffffffffu, dot1, 1);
        dot1 += __shfl_xor_sync(0xffffffffu, dot1, 2);
        if (tig == 0) {
            outLogp[row0 + s0] = -dot0;
            outLogp[row0 + s1] = -dot1;
        }
    }
}

// ---------------- launcher ----------------
extern "C" void kernel_launch(void* const* d_in, const int* in_sizes, int n_in,
                              void* d_out, int out_size)
{
    const float* t   = (const float*)d_in[0];
    const float* y   = (const float*)d_in[1];
    const float* h   = (const float*)d_in[3];
    const float* eps = (const float*)d_in[4];
    const float* W1  = (const float*)d_in[5];
    const float* b1  = (const float*)d_in[6];
    const float* W2  = (const float*)d_in[7];
    const float* b2  = (const float*)d_in[8];
    const float* W3  = (const float*)d_in[9];
    const float* b3  = (const float*)d_in[10];

    const int Bsz = in_sizes[1] / Dd;

    prep_weights<<<(T1ELEM + T2ELEM + T3ELEM + 255) / 256, 256>>>(W1, W2, W3);

    cudaFuncSetAttribute(odefunc_mma,
                         cudaFuncAttributeMaxDynamicSharedMemorySize, SM_TOT);
    odefunc_mma<<<Bsz / MROWS, THREADS, SM_TOT>>>(
        t, y, h, eps, b1, b2, b3, (float*)d_out, Bsz);
}

// round 4
// speedup vs baseline: 5.2524x; 3.2890x over previous
#include <cuda_runtime.h>
#include <cuda_fp16.h>
#include <cstdint>
#include <math.h>

// ---------------- constants ----------------
#define Dd      16
#define CTXd    128
#define SAMP    32            // samples per CTA
#define THREADS 256
#define STRB    384           // bytes per row (192 fp16) for W images and aBuf
#define WIMG    73728         // 192 rows * 384 B
#define W3IMG   6144          // 16 rows * 384 B

// smem layout (bytes)
#define SM_W    0             // weight image buffer (73728)
#define SM_A    73728         // activation buffer: 64 rows x 384 B (24576)
#define SM_G    98304         // gelu' buffer: 32 rows x 400 B (12800)
#define SM_BIAS 111104        // 192 fp32 (768)
#define SM_TOT  111872

// ---------------- weight images (pre-swizzled fp16) ----------------
__device__ __align__(16) uint8_t g_w1i[WIMG];
__device__ __align__(16) uint8_t g_w2i[WIMG];
__device__ __align__(16) uint8_t g_w3i[W3IMG];
__device__ float g_b1p[192];

// image write: row n, k-chunk XOR-swizzled within 128B groups
__device__ __forceinline__ void wimg_write(uint8_t* img, int n, int k, float v) {
    int chunk = (k >> 3) ^ (n & 7);
    *(__half*)(img + n * STRB + (chunk << 4) + (k & 7) * 2) = __float2half_rn(v);
}

__global__ void prep(const float* __restrict__ W1, const float* __restrict__ W2,
                     const float* __restrict__ W3, const float* __restrict__ b1,
                     const float* __restrict__ t)
{
    int idx = blockIdx.x * blockDim.x + threadIdx.x;
    if (idx < 27648) {                       // W1: k<144, n<192
        int k = idx / 192, n = idx - k * 192;
        wimg_write(g_w1i, n, k, W1[(size_t)k * 192 + n]);
    } else if (idx < 64512) {                // W2: 192x192
        int i = idx - 27648;
        int k = i / 192, n = i - k * 192;
        wimg_write(g_w2i, n, k, W2[(size_t)k * 192 + n]);
    } else if (idx < 67584) {                // W3: 192x16
        int i = idx - 64512;
        int k = i / 16, n = i - k * 16;
        wimg_write(g_w3i, n, k, W3[(size_t)k * 16 + n]);
    } else if (idx < 67776) {                // b1' = b1 + t*W1[144,:]
        int n = idx - 67584;
        g_b1p[n] = b1[n] + t[0] * W1[144 * 192 + n];
    }
}

// ---------------- PTX helpers ----------------
__device__ __forceinline__ uint32_t smem_u32(const void* p) {
    uint32_t a;
    asm("{ .reg .u64 t; cvta.to.shared.u64 t, %1; cvt.u32.u64 %0, t; }" : "=r"(a) : "l"(p));
    return a;
}
__device__ __forceinline__ void cpa16(uint32_t dst, const void* src) {
    asm volatile("cp.async.cg.shared.global [%0], [%1], 16;" :: "r"(dst), "l"(src) : "memory");
}
__device__ __forceinline__ void cpa_commit() {
    asm volatile("cp.async.commit_group;" ::: "memory");
}
__device__ __forceinline__ void cpa_wait_all() {
    asm volatile("cp.async.wait_group 0;" ::: "memory");
}
__device__ __forceinline__ void ldsm4(uint32_t (&r)[4], uint32_t addr) {
    asm volatile("ldmatrix.sync.aligned.m8n8.x4.shared.b16 {%0,%1,%2,%3}, [%4];"
                 : "=r"(r[0]), "=r"(r[1]), "=r"(r[2]), "=r"(r[3]) : "r"(addr));
}
__device__ __forceinline__ void mma16816(float (&d)[4], const uint32_t (&a)[4],
                                         uint32_t b0, uint32_t b1)
{
    asm volatile("mma.sync.aligned.m16n8k16.row.col.f32.f16.f16.f32 "
                 "{%0,%1,%2,%3}, {%4,%5,%6,%7}, {%8,%9}, {%0,%1,%2,%3};"
                 : "+f"(d[0]), "+f"(d[1]), "+f"(d[2]), "+f"(d[3])
                 : "r"(a[0]), "r"(a[1]), "r"(a[2]), "r"(a[3]), "r"(b0), "r"(b1));
}

// per-lane swizzled ldmatrix addresses (row-major A / col-major B images)
__device__ __forceinline__ uint32_t aAddr(uint32_t base, int m0, int kt, int lane) {
    int row = m0 + (lane & 7) + ((lane >> 3) & 1) * 8;
    int chunk = (kt * 2 + ((lane >> 4) & 1)) ^ (row & 7);
    return base + row * STRB + (chunk << 4);
}
__device__ __forceinline__ uint32_t bAddr(uint32_t base, int n0, int kt, int lane) {
    int row = n0 + (lane & 7) + ((lane >> 4) & 1) * 8;
    int chunk = (kt * 2 + ((lane >> 3) & 1)) ^ (row & 7);
    return base + row * STRB + (chunk << 4);
}

// one k-step for a 32x48 warp tile
__device__ __forceinline__ void kstep(float (&acc)[2][6][4], uint32_t aB, uint32_t wB,
                                      int m0, int n0, int kt, int lane)
{
    uint32_t a[2][4];
    ldsm4(a[0], aAddr(aB, m0,      kt, lane));
    ldsm4(a[1], aAddr(aB, m0 + 16, kt, lane));
#pragma unroll
    for (int np = 0; np < 3; np++) {
        uint32_t b[4];
        ldsm4(b, bAddr(wB, n0 + 16 * np, kt, lane));
#pragma unroll
        for (int mt = 0; mt < 2; mt++) {
            mma16816(acc[mt][2 * np],     a[mt], b[0], b[1]);
            mma16816(acc[mt][2 * np + 1], a[mt], b[2], b[3]);
        }
    }
}

// swizzled half2 store into an image-format smem buffer
__device__ __forceinline__ void stH2(char* sm, int off, int row, int c0, float v0, float v1) {
    int chunk = (c0 >> 3) ^ (row & 7);
    *(__half2*)(sm + off + row * STRB + (chunk << 4) + (c0 & 7) * 2) = __floats2half2_rn(v0, v1);
}

__device__ __forceinline__ void gelu2(float a0, float a1, float& g0, float& g1,
                                      float& p0, float& p1)
{
    float c0 = 0.5f * (1.0f + erff(a0 * 0.70710678118654752f));
    float c1 = 0.5f * (1.0f + erff(a1 * 0.70710678118654752f));
    float q0 = 0.3989422804014327f * __expf(-0.5f * a0 * a0);
    float q1 = 0.3989422804014327f * __expf(-0.5f * a1 * a1);
    g0 = a0 * c0;  g1 = a1 * c1;
    p0 = c0 + a0 * q0;  p1 = c1 + a1 * q1;
}

// ---------------- main kernel ----------------
__global__ void __launch_bounds__(THREADS, 2)
odefunc_mma2(const float* __restrict__ y,
             const float* __restrict__ h,
             const float* __restrict__ eps,
             const float* __restrict__ b2,
             const float* __restrict__ b3,
             float* __restrict__ out, int Bsz)
{
    extern __shared__ __align__(16) char smem[];
    const uint32_t sbase = smem_u32(smem);
    const uint32_t swW = sbase + SM_W;
    const uint32_t swA = sbase + SM_A;
    float* sBias = (float*)(smem + SM_BIAS);

    const int tid  = threadIdx.x;
    const int lane = tid & 31;
    const int w    = tid >> 5;
    const int mq   = w >> 2;        // 0 = primal rows 0-31, 1 = tangent rows 32-63
    const int nq   = w & 3;         // n-quarter (48 cols)
    const int m0   = mq * 32;
    const int n0   = nq * 48;

    const int row0 = blockIdx.x * SAMP;
    float* outF    = out;
    float* outLogp = out + (size_t)Bsz * Dd;
    float* outDh   = out + (size_t)Bsz * (Dd + 1);

    // ---- issue W1 copy immediately ----
    for (int i = tid; i < WIMG / 16; i += THREADS)
        cpa16(swW + i * 16, g_w1i + i * 16);
    cpa_commit();

    // bias1', zero dh, stage inputs (overlap the copy)
    if (tid < 192) sBias[tid] = g_b1p[tid];
    {
        float4* dhp = (float4*)(outDh + (size_t)row0 * CTXd);
        const float4 z4 = make_float4(0.f, 0.f, 0.f, 0.f);
        for (int i = tid; i < SAMP * CTXd / 4; i += THREADS) dhp[i] = z4;
    }
    // primal rows: [y(16) | h(128)] = K 144
    for (int i = tid; i < 2304; i += THREADS) {
        int s = i / 72, j = i - s * 72, k = 2 * j;
        float2 v;
        if (k < 16) v = *(const float2*)(y + (size_t)(row0 + s) * Dd + k);
        else        v = *(const float2*)(h + (size_t)(row0 + s) * CTXd + (k - 16));
        stH2(smem, SM_A, s, k, v.x, v.y);
    }
    // tangent rows: eps in k 0-15
    {
        int s = tid / 8, k = 2 * (tid & 7);
        float2 v = *(const float2*)(eps + (size_t)(row0 + s) * Dd + k);
        stH2(smem, SM_A, 32 + s, k, v.x, v.y);
    }
    cpa_wait_all();
    __syncthreads();

    // ---------------- layer 1 ----------------
    float acc[2][6][4];
#pragma unroll
    for (int i = 0; i < 2; i++)
#pragma unroll
        for (int j = 0; j < 6; j++)
#pragma unroll
            for (int q = 0; q < 4; q++) acc[i][j][q] = 0.f;

    if (mq == 0) {
#pragma unroll
        for (int kt = 0; kt < 9; kt++) kstep(acc, swA, swW, m0, n0, kt, lane);
    } else {
        kstep(acc, swA, swW, m0, n0, 0, lane);   // eps only lives in k<16
    }
    __syncthreads();

    // issue W2 copy; it hides under the epilogue
    for (int i = tid; i < WIMG / 16; i += THREADS)
        cpa16(swW + i * 16, g_w2i + i * 16);
    cpa_commit();

    // ---- epilogue 1 ----
#pragma unroll 1
    for (int layer = 0; layer < 2; layer++) {
        if (mq == 0) {  // primal: bias + gelu, stash gelu'
#pragma unroll
            for (int mt = 0; mt < 2; mt++)
#pragma unroll
                for (int nt = 0; nt < 6; nt++)
#pragma unroll
                    for (int rh = 0; rh < 2; rh++) {
                        int s  = 16 * mt + (lane >> 2) + 8 * rh;
                        int c0 = n0 + 8 * nt + 2 * (lane & 3);
                        float a0 = acc[mt][nt][2 * rh]     + sBias[c0];
                        float a1 = acc[mt][nt][2 * rh + 1] + sBias[c0 + 1];
                        float g0, g1, p0, p1;
                        gelu2(a0, a1, g0, g1, p0, p1);
                        stH2(smem, SM_A, s, c0, g0, g1);
                        *(__half2*)(smem + SM_G + s * 400 + c0 * 2) = __floats2half2_rn(p0, p1);
                    }
        }
        __syncthreads();
        if (mq == 1) {  // tangent: u * gelu'(a)
#pragma unroll
            for (int mt = 0; mt < 2; mt++)
#pragma unroll
                for (int nt = 0; nt < 6; nt++)
#pragma unroll
                    for (int rh = 0; rh < 2; rh++) {
                        int s  = 16 * mt + (lane >> 2) + 8 * rh;
                        int c0 = n0 + 8 * nt + 2 * (lane & 3);
                        __half2 gp = *(__half2*)(smem + SM_G + s * 400 + c0 * 2);
                        float2 gpf = __half22float2(gp);
                        float u0 = acc[mt][nt][2 * rh]     * gpf.x;
                        float u1 = acc[mt][nt][2 * rh + 1] * gpf.y;
                        stH2(smem, SM_A, 32 + s, c0, u0, u1);
                    }
        }
        if (layer == 0 && tid < 192) sBias[tid] = __ldg(b2 + tid);
        cpa_wait_all();
        __syncthreads();

        if (layer == 1) break;

        // ---------------- layer 2 ----------------
#pragma unroll
        for (int i = 0; i < 2; i++)
#pragma unroll
            for (int j = 0; j < 6; j++)
#pragma unroll
                for (int q = 0; q < 4; q++) acc[i][j][q] = 0.f;
#pragma unroll
        for (int kt = 0; kt < 12; kt++) kstep(acc, swA, swW, m0, n0, kt, lane);
        __syncthreads();

        // issue W3 copy; hides under epilogue 2
        for (int i = tid; i < W3IMG / 16; i += THREADS)
            cpa16(swW + i * 16, g_w3i + i * 16);
        cpa_commit();
    }

    // ---------------- layer 3 (N=16) + final outputs ----------------
    if (nq == 0) {
        float acc3[2][2][4];
#pragma unroll
        for (int i = 0; i < 2; i++)
#pragma unroll
            for (int j = 0; j < 2; j++)
#pragma unroll
                for (int q = 0; q < 4; q++) acc3[i][j][q] = 0.f;
#pragma unroll
        for (int kt = 0; kt < 12; kt++) {
            uint32_t a[2][4];
            ldsm4(a[0], aAddr(swA, m0,      kt, lane));
            ldsm4(a[1], aAddr(swA, m0 + 16, kt, lane));
            uint32_t b[4];
            ldsm4(b, bAddr(swW, 0, kt, lane));
#pragma unroll
            for (int mt = 0; mt < 2; mt++) {
                mma16816(acc3[mt][0], a[mt], b[0], b[1]);
                mma16816(acc3[mt][1], a[mt], b[2], b[3]);
            }
        }
        if (mq == 0) {  // f = z @ W3 + b3
#pragma unroll
            for (int mt = 0; mt < 2; mt++)
#pragma unroll
                for (int nt = 0; nt < 2; nt++)
#pragma unroll
                    for (int rh = 0; rh < 2; rh++) {
                        int s  = 16 * mt + (lane >> 2) + 8 * rh;
                        int c0 = 8 * nt + 2 * (lane & 3);
                        float2 o;
                        o.x = acc3[mt][nt][2 * rh]     + __ldg(b3 + c0);
                        o.y = acc3[mt][nt][2 * rh + 1] + __ldg(b3 + c0 + 1);
                        *(float2*)(outF + (size_t)(row0 + s) * Dd + c0) = o;
                    }
        } else {        // dlogp = -sum(Jeps * eps)
#pragma unroll
            for (int mt = 0; mt < 2; mt++)
#pragma unroll
                for (int rh = 0; rh < 2; rh++) {
                    int s = 16 * mt + (lane >> 2) + 8 * rh;
                    const float* erow = eps + (size_t)(row0 + s) * Dd;
                    float dot = 0.f;
#pragma unroll
                    for (int nt = 0; nt < 2; nt++) {
                        int c0 = 8 * nt + 2 * (lane & 3);
                        dot += acc3[mt][nt][2 * rh]     * __ldg(erow + c0)
                             + acc3[mt][nt][2 * rh + 1] * __ldg(erow + c0 + 1);
                    }
                    dot += __shfl_xor_sync(0xffffffffu, dot, 1);
                    dot += __shfl_xor_sync(0xffffffffu, dot, 2);
                    if ((lane & 3) == 0) outLogp[row0 + s] = -dot;
                }
        }
    }
}

// ---------------- launcher ----------------
extern "C" void kernel_launch(void* const* d_in, const int* in_sizes, int n_in,
                              void* d_out, int out_size)
{
    const float* t   = (const float*)d_in[0];
    const float* y   = (const float*)d_in[1];
    const float* h   = (const float*)d_in[3];
    const float* eps = (const float*)d_in[4];
    const float* W1  = (const float*)d_in[5];
    const float* b1  = (const float*)d_in[6];
    const float* W2  = (const float*)d_in[7];
    const float* b2  = (const float*)d_in[8];
    const float* W3  = (const float*)d_in[9];
    const float* b3  = (const float*)d_in[10];

    const int Bsz = in_sizes[1] / Dd;

    prep<<<(67776 + 255) / 256, 256>>>(W1, W2, W3, b1, t);

    cudaFuncSetAttribute(odefunc_mma2,
                         cudaFuncAttributeMaxDynamicSharedMemorySize, SM_TOT);
    odefunc_mma2<<<Bsz / SAMP, THREADS, SM_TOT>>>(
        y, h, eps, b2, b3, (float*)d_out, Bsz);
}

// round 5
// speedup vs baseline: 7.4913x; 1.4262x over previous
#include <cuda_runtime.h>
#include <cuda_fp16.h>
#include <cstdint>
#include <math.h>

// ---------------- constants ----------------
#define Dd      16
#define CTXd    128
#define SAMP    64
#define THREADS 512
#define STRB    384           // bytes per row (192 fp16)
#define WIMG    73728         // 192 rows * 384 B
#define W3IMG   6144          // 16 rows * 384 B

// smem layout (bytes)
#define SM_W    0             // weight image buffer (73728)
#define SM_RED  8192          // L3 partials (32KB), aliases dead W region
#define SM_A    73728         // activation buffer: 128 rows x 384 B (49152)
#define SM_BIAS 122880        // 384 fp32 (1536)
#define SM_TOT  124416

// ---------------- weight images (pre-swizzled fp16) ----------------
__device__ __align__(16) uint8_t g_w1i[WIMG];
__device__ __align__(16) uint8_t g_w2i[WIMG];
__device__ __align__(16) uint8_t g_w3i[W3IMG];
__device__ float g_b1p[192];

__device__ __forceinline__ void wimg_write(uint8_t* img, int n, int k, float v) {
    int chunk = (k >> 3) ^ (n & 7);
    *(__half*)(img + n * STRB + (chunk << 4) + (k & 7) * 2) = __float2half_rn(v);
}

__global__ void prep(const float* __restrict__ W1, const float* __restrict__ W2,
                     const float* __restrict__ W3, const float* __restrict__ b1,
                     const float* __restrict__ t)
{
    int idx = blockIdx.x * blockDim.x + threadIdx.x;
    if (idx < 27648) {                       // W1: k<144, n<192
        int k = idx / 192, n = idx - k * 192;
        wimg_write(g_w1i, n, k, W1[(size_t)k * 192 + n]);
    } else if (idx < 64512) {                // W2: 192x192
        int i = idx - 27648;
        int k = i / 192, n = i - k * 192;
        wimg_write(g_w2i, n, k, W2[(size_t)k * 192 + n]);
    } else if (idx < 67584) {                // W3: 192x16
        int i = idx - 64512;
        int k = i / 16, n = i - k * 16;
        wimg_write(g_w3i, n, k, W3[(size_t)k * 16 + n]);
    } else if (idx < 67776) {                // b1' = b1 + t*W1[144,:]
        int n = idx - 67584;
        g_b1p[n] = b1[n] + t[0] * W1[144 * 192 + n];
    }
}

// ---------------- PTX helpers ----------------
__device__ __forceinline__ uint32_t smem_u32(const void* p) {
    uint32_t a;
    asm("{ .reg .u64 t; cvta.to.shared.u64 t, %1; cvt.u32.u64 %0, t; }" : "=r"(a) : "l"(p));
    return a;
}
__device__ __forceinline__ void cpa16(uint32_t dst, const void* src) {
    asm volatile("cp.async.cg.shared.global [%0], [%1], 16;" :: "r"(dst), "l"(src) : "memory");
}
__device__ __forceinline__ void cpa_commit() {
    asm volatile("cp.async.commit_group;" ::: "memory");
}
__device__ __forceinline__ void cpa_wait_all() {
    asm volatile("cp.async.wait_group 0;" ::: "memory");
}
__device__ __forceinline__ void ldsm4(uint32_t (&r)[4], uint32_t addr) {
    asm volatile("ldmatrix.sync.aligned.m8n8.x4.shared.b16 {%0,%1,%2,%3}, [%4];"
                 : "=r"(r[0]), "=r"(r[1]), "=r"(r[2]), "=r"(r[3]) : "r"(addr));
}
__device__ __forceinline__ void mma16816(float (&d)[4], const uint32_t (&a)[4],
                                         uint32_t b0, uint32_t b1)
{
    asm volatile("mma.sync.aligned.m16n8k16.row.col.f32.f16.f16.f32 "
                 "{%0,%1,%2,%3}, {%4,%5,%6,%7}, {%8,%9}, {%0,%1,%2,%3};"
                 : "+f"(d[0]), "+f"(d[1]), "+f"(d[2]), "+f"(d[3])
                 : "r"(a[0]), "r"(a[1]), "r"(a[2]), "r"(a[3]), "r"(b0), "r"(b1));
}

__device__ __forceinline__ uint32_t aAddr(uint32_t base, int m0, int kt, int lane) {
    int row = m0 + (lane & 7) + ((lane >> 3) & 1) * 8;
    int chunk = (kt * 2 + ((lane >> 4) & 1)) ^ (row & 7);
    return base + row * STRB + (chunk << 4);
}
__device__ __forceinline__ uint32_t bAddr(uint32_t base, int n0, int kt, int lane) {
    int row = n0 + (lane & 7) + ((lane >> 4) & 1) * 8;
    int chunk = (kt * 2 + ((lane >> 3) & 1)) ^ (row & 7);
    return base + row * STRB + (chunk << 4);
}

__device__ __forceinline__ void stH2(char* sm, int off, int row, int c0, float v0, float v1) {
    int chunk = (c0 >> 3) ^ (row & 7);
    *(__half2*)(sm + off + row * STRB + (chunk << 4) + (c0 & 7) * 2) = __floats2half2_rn(v0, v1);
}

__device__ __forceinline__ void gelu2(float a0, float a1, float& g0, float& g1,
                                      float& p0, float& p1)
{
    float c0 = 0.5f * (1.0f + erff(a0 * 0.70710678118654752f));
    float c1 = 0.5f * (1.0f + erff(a1 * 0.70710678118654752f));
    float q0 = 0.3989422804014327f * __expf(-0.5f * a0 * a0);
    float q1 = 0.3989422804014327f * __expf(-0.5f * a1 * a1);
    g0 = a0 * c0;  g1 = a1 * c1;
    p0 = c0 + a0 * q0;  p1 = c1 + a1 * q1;
}

// local epilogue: bias + gelu on primal frag, gelu'(a)*u on tangent frag, both to smem A
__device__ __forceinline__ void epilogue(float (&accP)[6][4], float (&accT)[6][4],
                                         const float* bias, char* smem,
                                         int mh, int n0, int lane)
{
    const int r0 = mh * 16 + (lane >> 2);
    const int cl = 2 * (lane & 3);
#pragma unroll
    for (int nt = 0; nt < 6; nt++) {
        const int c0 = n0 + 8 * nt + cl;
        const float bb0 = bias[c0], bb1 = bias[c0 + 1];
#pragma unroll
        for (int rh = 0; rh < 2; rh++) {
            const int s = r0 + 8 * rh;
            float a0 = accP[nt][2 * rh]     + bb0;
            float a1 = accP[nt][2 * rh + 1] + bb1;
            float g0, g1, p0, p1;
            gelu2(a0, a1, g0, g1, p0, p1);
            stH2(smem, SM_A, s, c0, g0, g1);
            stH2(smem, SM_A, 64 + s, c0, accT[nt][2 * rh] * p0, accT[nt][2 * rh + 1] * p1);
        }
    }
}

// ---------------- main kernel ----------------
__global__ void __launch_bounds__(THREADS, 1)
odefunc_mma3(const float* __restrict__ y,
             const float* __restrict__ h,
             const float* __restrict__ eps,
             const float* __restrict__ b2,
             const float* __restrict__ b3,
             float* __restrict__ out, int Bsz)
{
    extern __shared__ __align__(16) char smem[];
    const uint32_t sbase = smem_u32(smem);
    const uint32_t swW = sbase + SM_W;
    const uint32_t swA = sbase + SM_A;
    float* sBias = (float*)(smem + SM_BIAS);
    float* sRed  = (float*)(smem + SM_RED);

    const int tid  = threadIdx.x;
    const int lane = tid & 31;
    const int w    = tid >> 5;          // 0..15
    const int nq   = w & 3;             // n-quarter (48 cols)
    const int mh   = w >> 2;            // m-group (16 rows) 0..3
    const int n0   = nq * 48;

    const int row0 = blockIdx.x * SAMP;
    float* outF    = out;
    float* outLogp = out + (size_t)Bsz * Dd;
    float* outDh   = out + (size_t)Bsz * (Dd + 1);

    // ---- stage: W1 copy + biases + zero dh + inputs ----
    for (int i = tid; i < WIMG / 16; i += THREADS)
        cpa16(swW + i * 16, g_w1i + i * 16);
    cpa_commit();

    if (tid < 192) sBias[tid] = g_b1p[tid];
    else if (tid >= 256 && tid < 448) sBias[tid - 64] = __ldg(b2 + (tid - 256));
    {
        float4* dhp = (float4*)(outDh + (size_t)row0 * CTXd);
        const float4 z4 = make_float4(0.f, 0.f, 0.f, 0.f);
        for (int i = tid; i < SAMP * CTXd / 4; i += THREADS) dhp[i] = z4;
    }
    {   // primal rows 0..63: [y(16) | h(128)] = K 144
        const int s = tid >> 3, kb = tid & 7;
#pragma unroll
        for (int j = 0; j < 9; j++) {
            const int k = 2 * (kb + 8 * j);
            float2 v;
            if (k < 16) v = *(const float2*)(y + (size_t)(row0 + s) * Dd + k);
            else        v = *(const float2*)(h + (size_t)(row0 + s) * CTXd + (k - 16));
            stH2(smem, SM_A, s, k, v.x, v.y);
        }
        // tangent rows 64..127: eps in k 0..15
        const int k = 2 * (tid & 7);
        float2 v = *(const float2*)(eps + (size_t)(row0 + s) * Dd + k);
        stH2(smem, SM_A, 64 + s, k, v.x, v.y);
    }
    cpa_wait_all();
    __syncthreads();

    // ---------------- layer 1 ----------------
    float accP[6][4], accT[6][4];
#pragma unroll
    for (int j = 0; j < 6; j++)
#pragma unroll
        for (int q = 0; q < 4; q++) { accP[j][q] = 0.f; accT[j][q] = 0.f; }

    {   // kt = 0: shared B for primal + tangent (eps lives only in k<16)
        uint32_t b[3][4], aP[4], aT[4];
#pragma unroll
        for (int np = 0; np < 3; np++) ldsm4(b[np], bAddr(swW, n0 + 16 * np, 0, lane));
        ldsm4(aP, aAddr(swA, mh * 16,      0, lane));
        ldsm4(aT, aAddr(swA, 64 + mh * 16, 0, lane));
#pragma unroll
        for (int np = 0; np < 3; np++) {
            mma16816(accP[2 * np],     aP, b[np][0], b[np][1]);
            mma16816(accP[2 * np + 1], aP, b[np][2], b[np][3]);
            mma16816(accT[2 * np],     aT, b[np][0], b[np][1]);
            mma16816(accT[2 * np + 1], aT, b[np][2], b[np][3]);
        }
    }
#pragma unroll
    for (int kt = 1; kt < 9; kt++) {
        uint32_t b[3][4], aP[4];
#pragma unroll
        for (int np = 0; np < 3; np++) ldsm4(b[np], bAddr(swW, n0 + 16 * np, kt, lane));
        ldsm4(aP, aAddr(swA, mh * 16, kt, lane));
#pragma unroll
        for (int np = 0; np < 3; np++) {
            mma16816(accP[2 * np],     aP, b[np][0], b[np][1]);
            mma16816(accP[2 * np + 1], aP, b[np][2], b[np][3]);
        }
    }
    __syncthreads();                      // all W1 reads done

    for (int i = tid; i < WIMG / 16; i += THREADS)
        cpa16(swW + i * 16, g_w2i + i * 16);
    cpa_commit();

    epilogue(accP, accT, sBias, smem, mh, n0, lane);   // overlaps W2 copy
    cpa_wait_all();
    __syncthreads();

    // ---------------- layer 2 ----------------
#pragma unroll
    for (int j = 0; j < 6; j++)
#pragma unroll
        for (int q = 0; q < 4; q++) { accP[j][q] = 0.f; accT[j][q] = 0.f; }
#pragma unroll
    for (int kt = 0; kt < 12; kt++) {
        uint32_t b[3][4], aP[4], aT[4];
#pragma unroll
        for (int np = 0; np < 3; np++) ldsm4(b[np], bAddr(swW, n0 + 16 * np, kt, lane));
        ldsm4(aP, aAddr(swA, mh * 16,      kt, lane));
        ldsm4(aT, aAddr(swA, 64 + mh * 16, kt, lane));
#pragma unroll
        for (int np = 0; np < 3; np++) {
            mma16816(accP[2 * np],     aP, b[np][0], b[np][1]);
            mma16816(accP[2 * np + 1], aP, b[np][2], b[np][3]);
            mma16816(accT[2 * np],     aT, b[np][0], b[np][1]);
            mma16816(accT[2 * np + 1], aT, b[np][2], b[np][3]);
        }
    }
    __syncthreads();                      // all W2 reads done

    for (int i = tid; i < W3IMG / 16; i += THREADS)
        cpa16(swW + i * 16, g_w3i + i * 16);
    cpa_commit();

    epilogue(accP, accT, sBias + 192, smem, mh, n0, lane);   // overlaps W3 copy
    cpa_wait_all();
    __syncthreads();

    // ---------------- layer 3 (N=16), K split across warps ----------------
    {
        const int rowsel = (w >> 3) & 1;       // 0 = primal, 1 = tangent
        const int mh2    = (w >> 2) & 1;       // 32-row half
        const int kq     = w & 3;              // K quarter (3 ksteps)
        const int mbase  = rowsel * 64 + mh2 * 32;

        float acc3[2][2][4];
#pragma unroll
        for (int i = 0; i < 2; i++)
#pragma unroll
            for (int j = 0; j < 2; j++)
#pragma unroll
                for (int q = 0; q < 4; q++) acc3[i][j][q] = 0.f;
#pragma unroll
        for (int j = 0; j < 3; j++) {
            const int kt = kq * 3 + j;
            uint32_t b[4], a0[4], a1[4];
            ldsm4(b,  bAddr(swW, 0, kt, lane));
            ldsm4(a0, aAddr(swA, mbase,      kt, lane));
            ldsm4(a1, aAddr(swA, mbase + 16, kt, lane));
            mma16816(acc3[0][0], a0, b[0], b[1]);
            mma16816(acc3[0][1], a0, b[2], b[3]);
            mma16816(acc3[1][0], a1, b[0], b[1]);
            mma16816(acc3[1][1], a1, b[2], b[3]);
        }
        // partial sums -> sRed[(rowsel*4+kq)][64 rows][16]
        float* red = sRed + (rowsel * 4 + kq) * 1024;
        const int rbase = mh2 * 32 + (lane >> 2);
        const int cl = 2 * (lane & 3);
#pragma unroll
        for (int mt = 0; mt < 2; mt++)
#pragma unroll
            for (int nt = 0; nt < 2; nt++)
#pragma unroll
                for (int rh = 0; rh < 2; rh++) {
                    const int r = rbase + 16 * mt + 8 * rh;
                    const int c = 8 * nt + cl;
                    *(float2*)(red + r * 16 + c) =
                        make_float2(acc3[mt][nt][2 * rh], acc3[mt][nt][2 * rh + 1]);
                }
    }
    __syncthreads();

    // ---------------- reduce partials -> outputs ----------------
    // f = z2 @ W3 + b3
    for (int i = tid; i < SAMP * 16; i += THREADS) {
        const int s = i >> 4, c = i & 15;
        float v = sRed[s * 16 + c] + sRed[1024 + s * 16 + c]
                + sRed[2048 + s * 16 + c] + sRed[3072 + s * 16 + c];
        outF[(size_t)(row0 + s) * Dd + c] = v + __ldg(b3 + c);
    }
    // dlogp = -sum(Jeps * eps)
    {
        const int s = tid >> 3, g = tid & 7, c0 = 2 * g;
        const float* rt_ = sRed + 4096 + s * 16 + c0;
        float j0 = rt_[0] + rt_[1024] + rt_[2048] + rt_[3072];
        float j1 = rt_[1] + rt_[1025] + rt_[2049] + rt_[3073];
        float2 ev = *(const float2*)(eps + (size_t)(row0 + s) * Dd + c0);
        float dot = j0 * ev.x + j1 * ev.y;
        dot += __shfl_xor_sync(0xffffffffu, dot, 1);
        dot += __shfl_xor_sync(0xffffffffu, dot, 2);
        dot += __shfl_xor_sync(0xffffffffu, dot, 4);
        if (g == 0) outLogp[row0 + s] = -dot;
    }
}

// ---------------- launcher ----------------
extern "C" void kernel_launch(void* const* d_in, const int* in_sizes, int n_in,
                              void* d_out, int out_size)
{
    const float* t   = (const float*)d_in[0];
    const float* y   = (const float*)d_in[1];
    const float* h   = (const float*)d_in[3];
    const float* eps = (const float*)d_in[4];
    const float* W1  = (const float*)d_in[5];
    const float* b1  = (const float*)d_in[6];
    const float* W2  = (const float*)d_in[7];
    const float* b2  = (const float*)d_in[8];
    const float* W3  = (const float*)d_in[9];
    const float* b3  = (const float*)d_in[10];

    const int Bsz = in_sizes[1] / Dd;

    prep<<<(67776 + 255) / 256, 256>>>(W1, W2, W3, b1, t);

    cudaFuncSetAttribute(odefunc_mma3,
                         cudaFuncAttributeMaxDynamicSharedMemorySize, SM_TOT);
    odefunc_mma3<<<Bsz / SAMP, THREADS, SM_TOT>>>(
        y, h, eps, b2, b3, (float*)d_out, Bsz);
}